// round 2
// baseline (speedup 1.0000x reference)
#include <cuda_runtime.h>

#define THREADS 128
#define BWARPS 4

typedef unsigned long long ull;

__device__ __forceinline__ ull pack2(float lo, float hi) {
    ull r; asm("mov.b64 %0, {%1, %2};" : "=l"(r) : "f"(lo), "f"(hi)); return r;
}
__device__ __forceinline__ void unpack2(ull v, float& lo, float& hi) {
    asm("mov.b64 {%0, %1}, %2;" : "=f"(lo), "=f"(hi) : "l"(v));
}
__device__ __forceinline__ ull ffma2(ull a, ull b, ull c) {
    ull d; asm("fma.rn.f32x2 %0, %1, %2, %3;" : "=l"(d) : "l"(a), "l"(b), "l"(c)); return d;
}

__global__ void __launch_bounds__(THREADS, 3) edge_mlp_kernel(
    const float* __restrict__ src, const float* __restrict__ dst,
    const float* __restrict__ eat, const float* __restrict__ u,
    const int*   __restrict__ batch,     // int32 graph index per edge
    const float* __restrict__ W1, const float* __restrict__ b1,
    const float* __restrict__ W2, const float* __restrict__ b2,
    float* __restrict__ out, int E, int B)
{
    __shared__ __align__(16) float u_s[4096];
    __shared__ __align__(16) float W2p[10 * 20];   // [10][19] padded to stride 20 (8B-aligned k-pairs)
    __shared__ __align__(16) float b2s[20];
    __shared__ __align__(16) float stg[BWARPS][64 * 19];

    const int t = threadIdx.x;
    const int Bc = (B < 4096) ? B : 4096;

    for (int i = t; i < Bc; i += THREADS) u_s[i] = u[i];
    for (int i = t; i < 190; i += THREADS) W2p[(i / 19) * 20 + (i % 19)] = W2[i];
    for (int i = t; i < 19; i += THREADS) b2s[i] = b2[i];

    // Persistent register weights for layer 1
    float w1r[40], b1r[10];
#pragma unroll
    for (int i = 0; i < 40; i++) w1r[i] = __ldg(&W1[i]);
#pragma unroll
    for (int j = 0; j < 10; j++) b1r[j] = __ldg(&b1[j]);
    __syncthreads();

    const int warp = t >> 5, lane = t & 31;
    const int wg = blockIdx.x * BWARPS + warp;
    const int nw = gridDim.x * BWARPS;
    const int ntiles = (E + 63) >> 6;
    float* myst = stg[warp];

    for (int tile = wg; tile < ntiles; tile += nw) {
        const int base = tile << 6;
        if (base + 64 <= E) {
            const int e0i = base + lane, e1i = base + 32 + lane;
            // Coalesced input loads (2 edges per thread)
            const float s0 = src[e0i], s1 = src[e1i];
            const float d0 = dst[e0i], d1 = dst[e1i];
            const float a0 = eat[e0i], a1 = eat[e1i];
            const int i0 = batch[e0i], i1 = batch[e1i];
            const float u0 = ((unsigned)i0 < (unsigned)Bc) ? u_s[i0] : __ldg(&u[i0]);
            const float u1 = ((unsigned)i1 < (unsigned)Bc) ? u_s[i1] : __ldg(&u[i1]);

            // Layer 1: h = relu(x @ W1 + b1), scalar FFMA
            float h0[10], h1[10];
#pragma unroll
            for (int j = 0; j < 10; j++) {
                float x0 = fmaf(s0, w1r[j], fmaf(d0, w1r[10 + j],
                           fmaf(a0, w1r[20 + j], fmaf(u0, w1r[30 + j], b1r[j]))));
                float x1 = fmaf(s1, w1r[j], fmaf(d1, w1r[10 + j],
                           fmaf(a1, w1r[20 + j], fmaf(u1, w1r[30 + j], b1r[j]))));
                h0[j] = fmaxf(x0, 0.f);
                h1[j] = fmaxf(x1, 0.f);
            }

            // Layer 2, odd leftover column k=18 (scalar)
            {
                float acc0 = b2s[18], acc1 = b2s[18];
#pragma unroll
                for (int j = 0; j < 10; j++) {
                    float w = W2p[j * 20 + 18];
                    acc0 = fmaf(h0[j], w, acc0);
                    acc1 = fmaf(h1[j], w, acc1);
                }
                myst[lane * 19 + 18] = acc0;
                myst[(lane + 32) * 19 + 18] = acc1;
            }

            // Pack h broadcast pairs once, reused across all 9 k-pairs
            ull ph0[10], ph1[10];
#pragma unroll
            for (int j = 0; j < 10; j++) {
                ph0[j] = pack2(h0[j], h0[j]);
                ph1[j] = pack2(h1[j], h1[j]);
            }

            // Layer 2: 9 packed k-pairs via fma.rn.f32x2 (weight pairs contiguous in smem)
#pragma unroll
            for (int kp = 0; kp < 9; kp++) {
                const ull bb = *(const ull*)&b2s[2 * kp];
                ull acc0 = bb, acc1 = bb;
#pragma unroll
                for (int j = 0; j < 10; j++) {
                    const ull w = *(const ull*)&W2p[j * 20 + 2 * kp];
                    acc0 = ffma2(ph0[j], w, acc0);
                    acc1 = ffma2(ph1[j], w, acc1);
                }
                float lo, hi;
                unpack2(acc0, lo, hi);
                myst[lane * 19 + 2 * kp] = lo;
                myst[lane * 19 + 2 * kp + 1] = hi;
                unpack2(acc1, lo, hi);
                myst[(lane + 32) * 19 + 2 * kp] = lo;
                myst[(lane + 32) * 19 + 2 * kp + 1] = hi;
            }

            __syncwarp();
            // Coalesced float4 copy-out: 64*19 floats = 304 float4, base 16B-aligned
            const float4* s4 = (const float4*)myst;
            float4* o4 = (float4*)(out + (size_t)base * 19);
#pragma unroll 1
            for (int i = lane; i < 304; i += 32) o4[i] = s4[i];
            __syncwarp();
        } else {
            // Tail tile (E % 64): scalar fallback
            for (int e = base + lane; e < E; e += 32) {
                float s = src[e], d = dst[e], a = eat[e];
                int bi = batch[e];
                float uu = ((unsigned)bi < (unsigned)Bc) ? u_s[bi] : __ldg(&u[bi]);
                float h[10];
#pragma unroll
                for (int j = 0; j < 10; j++) {
                    float x = fmaf(s, w1r[j], fmaf(d, w1r[10 + j],
                              fmaf(a, w1r[20 + j], fmaf(uu, w1r[30 + j], b1r[j]))));
                    h[j] = fmaxf(x, 0.f);
                }
#pragma unroll
                for (int k = 0; k < 19; k++) {
                    float acc = b2s[k];
#pragma unroll
                    for (int j = 0; j < 10; j++) acc = fmaf(h[j], W2p[j * 20 + k], acc);
                    out[(size_t)e * 19 + k] = acc;
                }
            }
        }
    }
}

extern "C" void kernel_launch(void* const* d_in, const int* in_sizes, int n_in,
                              void* d_out, int out_size) {
    const float* src   = (const float*)d_in[0];
    const float* dst   = (const float*)d_in[1];
    const float* eat   = (const float*)d_in[2];
    const float* u     = (const float*)d_in[3];
    const int*   batch = (const int*)d_in[4];   // int64 in reference, int32 on device
    const float* W1    = (const float*)d_in[5];
    const float* b1    = (const float*)d_in[6];
    const float* W2    = (const float*)d_in[7];
    const float* b2    = (const float*)d_in[8];
    const int E = in_sizes[0];
    const int B = in_sizes[3];

    edge_mlp_kernel<<<444, THREADS>>>(src, dst, eat, u, batch,
                                      W1, b1, W2, b2, (float*)d_out, E, B);
}

// round 3
// speedup vs baseline: 1.0072x; 1.0072x over previous
#include <cuda_runtime.h>

#define THREADS 128
#define BWARPS 4

typedef unsigned long long ull;

__device__ __forceinline__ ull pack2(float lo, float hi) {
    ull r; asm("mov.b64 %0, {%1, %2};" : "=l"(r) : "f"(lo), "f"(hi)); return r;
}
__device__ __forceinline__ void unpack2(ull v, float& lo, float& hi) {
    asm("mov.b64 {%0, %1}, %2;" : "=f"(lo), "=f"(hi) : "l"(v));
}
__device__ __forceinline__ ull ffma2(ull a, ull b, ull c) {
    ull d; asm("fma.rn.f32x2 %0, %1, %2, %3;" : "=l"(d) : "l"(a), "l"(b), "l"(c)); return d;
}

__global__ void __launch_bounds__(THREADS, 4) edge_mlp_kernel(
    const float* __restrict__ src, const float* __restrict__ dst,
    const float* __restrict__ eat, const float* __restrict__ u,
    const int*   __restrict__ batch,
    const float* __restrict__ W1, const float* __restrict__ b1,
    const float* __restrict__ W2, const float* __restrict__ b2,
    float* __restrict__ out, int E, int B)
{
    __shared__ __align__(16) float u_s[4096];
    __shared__ __align__(16) float W1s[4][12];    // rows padded to 12 (48B, 16B-aligned)
    __shared__ __align__(16) float W2p[10][20];   // cols padded to 20; col 19 = 0
    __shared__ __align__(16) float b2s[20];       // [19] = 0
    __shared__ __align__(16) float stg[BWARPS][64 * 19];

    const int t = threadIdx.x;
    const int Bc = (B < 4096) ? B : 4096;

    for (int i = t; i < Bc; i += THREADS) u_s[i] = u[i];
    if (t < 48) W1s[t / 12][t % 12] = ((t % 12) < 10) ? W1[(t / 12) * 10 + (t % 12)] : 0.f;
    for (int i = t; i < 200; i += THREADS) {
        int j = i / 20, k = i % 20;
        W2p[j][k] = (k < 19) ? W2[j * 19 + k] : 0.f;
    }
    if (t < 20) b2s[t] = (t < 19) ? b2[t] : 0.f;

    float b1r[10];
#pragma unroll
    for (int j = 0; j < 10; j++) b1r[j] = __ldg(&b1[j]);
    __syncthreads();

    const int warp = t >> 5, lane = t & 31;
    const int wg = blockIdx.x * BWARPS + warp;
    const int nw = gridDim.x * BWARPS;
    const int ntiles = (E + 63) >> 6;
    float* myst = stg[warp];

    for (int tile = wg; tile < ntiles; tile += nw) {
        const int base = tile << 6;
        if (base + 64 <= E) {
            const int e0i = base + lane, e1i = base + 32 + lane;
            const float s0 = src[e0i], s1 = src[e1i];
            const float d0 = dst[e0i], d1 = dst[e1i];
            const float a0 = eat[e0i], a1 = eat[e1i];
            const int i0 = batch[e0i], i1 = batch[e1i];
            const float u0 = ((unsigned)i0 < (unsigned)Bc) ? u_s[i0] : __ldg(&u[i0]);
            const float u1 = ((unsigned)i1 < (unsigned)Bc) ? u_s[i1] : __ldg(&u[i1]);

            const float f0[4] = {s0, d0, a0, u0};
            const float f1[4] = {s1, d1, a1, u1};

            // Layer 1: x = b1 + sum_f feat_f * W1[f][:], weights via uniform LDS.128
            float x0[10], x1[10];
#pragma unroll
            for (int j = 0; j < 10; j++) { x0[j] = b1r[j]; x1[j] = b1r[j]; }
#pragma unroll
            for (int f = 0; f < 4; f++) {
                const float4 wA = *(const float4*)&W1s[f][0];
                const float4 wB = *(const float4*)&W1s[f][4];
                const float4 wC = *(const float4*)&W1s[f][8];
                const float v0 = f0[f], v1 = f1[f];
                x0[0] = fmaf(v0, wA.x, x0[0]); x1[0] = fmaf(v1, wA.x, x1[0]);
                x0[1] = fmaf(v0, wA.y, x0[1]); x1[1] = fmaf(v1, wA.y, x1[1]);
                x0[2] = fmaf(v0, wA.z, x0[2]); x1[2] = fmaf(v1, wA.z, x1[2]);
                x0[3] = fmaf(v0, wA.w, x0[3]); x1[3] = fmaf(v1, wA.w, x1[3]);
                x0[4] = fmaf(v0, wB.x, x0[4]); x1[4] = fmaf(v1, wB.x, x1[4]);
                x0[5] = fmaf(v0, wB.y, x0[5]); x1[5] = fmaf(v1, wB.y, x1[5]);
                x0[6] = fmaf(v0, wB.z, x0[6]); x1[6] = fmaf(v1, wB.z, x1[6]);
                x0[7] = fmaf(v0, wB.w, x0[7]); x1[7] = fmaf(v1, wB.w, x1[7]);
                x0[8] = fmaf(v0, wC.x, x0[8]); x1[8] = fmaf(v1, wC.x, x1[8]);
                x0[9] = fmaf(v0, wC.y, x0[9]); x1[9] = fmaf(v1, wC.y, x1[9]);
            }

            // ReLU + broadcast-pack (h, h)
            ull ph0[10], ph1[10];
#pragma unroll
            for (int j = 0; j < 10; j++) {
                float h0 = fmaxf(x0[j], 0.f), h1 = fmaxf(x1[j], 0.f);
                ph0[j] = pack2(h0, h0);
                ph1[j] = pack2(h1, h1);
            }

            // Layer 2: 5 groups of 4 output columns; weights via uniform LDS.128 -> ull pairs
#pragma unroll
            for (int kg = 0; kg < 5; kg++) {
                const int k0 = kg * 4;
                const ulonglong2 bb = *(const ulonglong2*)&b2s[k0];
                ull a00 = bb.x, a01 = bb.y;   // edge0: (k0,k0+1), (k0+2,k0+3)
                ull a10 = bb.x, a11 = bb.y;   // edge1
#pragma unroll
                for (int j = 0; j < 10; j++) {
                    const ulonglong2 w = *(const ulonglong2*)&W2p[j][k0];
                    a00 = ffma2(ph0[j], w.x, a00);
                    a01 = ffma2(ph0[j], w.y, a01);
                    a10 = ffma2(ph1[j], w.x, a10);
                    a11 = ffma2(ph1[j], w.y, a11);
                }
                float p, q;
                unpack2(a00, p, q);
                myst[lane * 19 + k0] = p; myst[lane * 19 + k0 + 1] = q;
                unpack2(a10, p, q);
                myst[(lane + 32) * 19 + k0] = p; myst[(lane + 32) * 19 + k0 + 1] = q;
                unpack2(a01, p, q);
                myst[lane * 19 + k0 + 2] = p;
                if (kg < 4) myst[lane * 19 + k0 + 3] = q;   // k=19 is pad
                unpack2(a11, p, q);
                myst[(lane + 32) * 19 + k0 + 2] = p;
                if (kg < 4) myst[(lane + 32) * 19 + k0 + 3] = q;
            }

            __syncwarp();
            const float4* s4 = (const float4*)myst;
            float4* o4 = (float4*)(out + (size_t)base * 19);
#pragma unroll 1
            for (int i = lane; i < 304; i += 32) o4[i] = s4[i];
            __syncwarp();
        } else {
            // Tail tile
            for (int e = base + lane; e < E; e += 32) {
                float s = src[e], d = dst[e], a = eat[e];
                int bi = batch[e];
                float uu = ((unsigned)bi < (unsigned)Bc) ? u_s[bi] : __ldg(&u[bi]);
                float feat[4] = {s, d, a, uu};
                float h[10];
#pragma unroll
                for (int j = 0; j < 10; j++) {
                    float x = b1r[j];
#pragma unroll
                    for (int f = 0; f < 4; f++) x = fmaf(feat[f], W1s[f][j], x);
                    h[j] = fmaxf(x, 0.f);
                }
#pragma unroll
                for (int k = 0; k < 19; k++) {
                    float acc = b2s[k];
#pragma unroll
                    for (int j = 0; j < 10; j++) acc = fmaf(h[j], W2p[j][k], acc);
                    out[(size_t)e * 19 + k] = acc;
                }
            }
        }
    }
}

extern "C" void kernel_launch(void* const* d_in, const int* in_sizes, int n_in,
                              void* d_out, int out_size) {
    const float* src   = (const float*)d_in[0];
    const float* dst   = (const float*)d_in[1];
    const float* eat   = (const float*)d_in[2];
    const float* u     = (const float*)d_in[3];
    const int*   batch = (const int*)d_in[4];
    const float* W1    = (const float*)d_in[5];
    const float* b1    = (const float*)d_in[6];
    const float* W2    = (const float*)d_in[7];
    const float* b2    = (const float*)d_in[8];
    const int E = in_sizes[0];
    const int B = in_sizes[3];

    edge_mlp_kernel<<<740, THREADS>>>(src, dst, eat, u, batch,
                                      W1, b1, W2, b2, (float*)d_out, E, B);
}

// round 5
// speedup vs baseline: 1.3982x; 1.3883x over previous
#include <cuda_runtime.h>

#define THREADS 128
#define BWARPS 4

typedef unsigned long long ull;

__device__ __forceinline__ ull pack2(float lo, float hi) {
    ull r; asm("mov.b64 %0, {%1, %2};" : "=l"(r) : "f"(lo), "f"(hi)); return r;
}
__device__ __forceinline__ void unpack2(ull v, float& lo, float& hi) {
    asm("mov.b64 {%0, %1}, %2;" : "=f"(lo), "=f"(hi) : "l"(v));
}
__device__ __forceinline__ ull ffma2(ull a, ull b, ull c) {
    ull d; asm("fma.rn.f32x2 %0, %1, %2, %3;" : "=l"(d) : "l"(a), "l"(b), "l"(c)); return d;
}

__global__ void __launch_bounds__(THREADS, 4) edge_mlp_kernel(
    const float* __restrict__ src, const float* __restrict__ dst,
    const float* __restrict__ eat, const float* __restrict__ u,
    const int*   __restrict__ batch,
    const float* __restrict__ W1, const float* __restrict__ b1,
    const float* __restrict__ W2, const float* __restrict__ b2,
    float* __restrict__ out, int E, int B)
{
    __shared__ __align__(16) float u_s[4096];
    __shared__ __align__(16) float W1s[5][12];    // rows 0-3 = W1, row 4 = b1 (bias as feature 1.0)
    __shared__ __align__(16) float W2p[10][20];   // cols padded to 20; col 19 = 0
    __shared__ __align__(16) float b2s[20];       // [19] = 0
    __shared__ __align__(16) float stg[BWARPS][64 * 19];

    const int t = threadIdx.x;
    const int Bc = (B < 4096) ? B : 4096;

    for (int i = t; i < Bc; i += THREADS) u_s[i] = u[i];
    if (t < 60) {
        int f = t / 12, j = t % 12;
        float v = 0.f;
        if (j < 10) v = (f < 4) ? W1[f * 10 + j] : b1[j];
        W1s[f][j] = v;
    }
    for (int i = t; i < 200; i += THREADS) {
        int j = i / 20, k = i % 20;
        W2p[j][k] = (k < 19) ? W2[j * 19 + k] : 0.f;
    }
    if (t < 20) b2s[t] = (t < 19) ? b2[t] : 0.f;
    __syncthreads();

    const int warp = t >> 5, lane = t & 31;
    const int wg = blockIdx.x * BWARPS + warp;
    const int nw = gridDim.x * BWARPS;
    const int ntiles = (E + 127) >> 7;   // 128-edge tiles
    float* myst = stg[warp];

    for (int tile = wg; tile < ntiles; tile += nw) {
        const int base = tile << 7;
        if (base + 128 <= E) {
            // Front-batch ALL loads for 4 edges/thread (2x MLP in flight)
            float sv[4], dv[4], av[4], uv[4];
            int iv[4];
#pragma unroll
            for (int q = 0; q < 4; q++) {
                const int e = base + q * 32 + lane;
                sv[q] = src[e]; dv[q] = dst[e]; av[q] = eat[e]; iv[q] = batch[e];
            }
#pragma unroll
            for (int q = 0; q < 4; q++)
                uv[q] = ((unsigned)iv[q] < (unsigned)Bc) ? u_s[iv[q]] : __ldg(&u[iv[q]]);

#pragma unroll
            for (int p = 0; p < 2; p++) {
                const float f0[5] = {sv[2 * p], dv[2 * p], av[2 * p], uv[2 * p], 1.f};
                const float f1[5] = {sv[2 * p + 1], dv[2 * p + 1], av[2 * p + 1], uv[2 * p + 1], 1.f};

                // Layer 1 (bias folded as feature 4), uniform LDS.128 weights
                float x0[10] = {0, 0, 0, 0, 0, 0, 0, 0, 0, 0};
                float x1[10] = {0, 0, 0, 0, 0, 0, 0, 0, 0, 0};
#pragma unroll
                for (int f = 0; f < 5; f++) {
                    const float4 wA = *(const float4*)&W1s[f][0];
                    const float4 wB = *(const float4*)&W1s[f][4];
                    const float4 wC = *(const float4*)&W1s[f][8];
                    const float v0 = f0[f], v1 = f1[f];
                    x0[0] = fmaf(v0, wA.x, x0[0]); x1[0] = fmaf(v1, wA.x, x1[0]);
                    x0[1] = fmaf(v0, wA.y, x0[1]); x1[1] = fmaf(v1, wA.y, x1[1]);
                    x0[2] = fmaf(v0, wA.z, x0[2]); x1[2] = fmaf(v1, wA.z, x1[2]);
                    x0[3] = fmaf(v0, wA.w, x0[3]); x1[3] = fmaf(v1, wA.w, x1[3]);
                    x0[4] = fmaf(v0, wB.x, x0[4]); x1[4] = fmaf(v1, wB.x, x1[4]);
                    x0[5] = fmaf(v0, wB.y, x0[5]); x1[5] = fmaf(v1, wB.y, x1[5]);
                    x0[6] = fmaf(v0, wB.z, x0[6]); x1[6] = fmaf(v1, wB.z, x1[6]);
                    x0[7] = fmaf(v0, wB.w, x0[7]); x1[7] = fmaf(v1, wB.w, x1[7]);
                    x0[8] = fmaf(v0, wC.x, x0[8]); x1[8] = fmaf(v1, wC.x, x1[8]);
                    x0[9] = fmaf(v0, wC.y, x0[9]); x1[9] = fmaf(v1, wC.y, x1[9]);
                }

                // ReLU + broadcast-pack
                ull ph0[10], ph1[10];
#pragma unroll
                for (int j = 0; j < 10; j++) {
                    float h0 = fmaxf(x0[j], 0.f), h1 = fmaxf(x1[j], 0.f);
                    ph0[j] = pack2(h0, h0);
                    ph1[j] = pack2(h1, h1);
                }

                // Layer 2: 5 groups of 4 columns via fma.rn.f32x2
#pragma unroll
                for (int kg = 0; kg < 5; kg++) {
                    const int k0 = kg * 4;
                    const ulonglong2 bb = *(const ulonglong2*)&b2s[k0];
                    ull a00 = bb.x, a01 = bb.y;
                    ull a10 = bb.x, a11 = bb.y;
#pragma unroll
                    for (int j = 0; j < 10; j++) {
                        const ulonglong2 w = *(const ulonglong2*)&W2p[j][k0];
                        a00 = ffma2(ph0[j], w.x, a00);
                        a01 = ffma2(ph0[j], w.y, a01);
                        a10 = ffma2(ph1[j], w.x, a10);
                        a11 = ffma2(ph1[j], w.y, a11);
                    }
                    float pp, qq;
                    unpack2(a00, pp, qq);
                    myst[lane * 19 + k0] = pp; myst[lane * 19 + k0 + 1] = qq;
                    unpack2(a10, pp, qq);
                    myst[(lane + 32) * 19 + k0] = pp; myst[(lane + 32) * 19 + k0 + 1] = qq;
                    unpack2(a01, pp, qq);
                    myst[lane * 19 + k0 + 2] = pp;
                    if (kg < 4) myst[lane * 19 + k0 + 3] = qq;
                    unpack2(a11, pp, qq);
                    myst[(lane + 32) * 19 + k0 + 2] = pp;
                    if (kg < 4) myst[(lane + 32) * 19 + k0 + 3] = qq;
                }

                __syncwarp();
                // Copy out this 64-edge half: 64*19 = 1216 floats = 304 float4
                const float4* s4 = (const float4*)myst;
                float4* o4 = (float4*)(out + (size_t)(base + p * 64) * 19);
#pragma unroll 1
                for (int i = lane; i < 304; i += 32) o4[i] = s4[i];
                __syncwarp();
            }
        } else {
            // Tail tile
            for (int e = base + lane; e < E; e += 32) {
                float s = src[e], d = dst[e], a = eat[e];
                int bi = batch[e];
                float uu = ((unsigned)bi < (unsigned)Bc) ? u_s[bi] : __ldg(&u[bi]);
                float feat[5] = {s, d, a, uu, 1.f};
                float h[10];
#pragma unroll
                for (int j = 0; j < 10; j++) {
                    float x = 0.f;
#pragma unroll
                    for (int f = 0; f < 5; f++) x = fmaf(feat[f], W1s[f][j], x);
                    h[j] = fmaxf(x, 0.f);
                }
#pragma unroll
                for (int k = 0; k < 19; k++) {
                    float acc = b2s[k];
#pragma unroll
                    for (int j = 0; j < 10; j++) acc = fmaf(h[j], W2p[j][k], acc);
                    out[(size_t)e * 19 + k] = acc;
                }
            }
        }
    }
}

extern "C" void kernel_launch(void* const* d_in, const int* in_sizes, int n_in,
                              void* d_out, int out_size) {
    const float* src   = (const float*)d_in[0];
    const float* dst   = (const float*)d_in[1];
    const float* eat   = (const float*)d_in[2];
    const float* u     = (const float*)d_in[3];
    const int*   batch = (const int*)d_in[4];
    const float* W1    = (const float*)d_in[5];
    const float* b1    = (const float*)d_in[6];
    const float* W2    = (const float*)d_in[7];
    const float* b2    = (const float*)d_in[8];
    const int E = in_sizes[0];
    const int B = in_sizes[3];

    edge_mlp_kernel<<<592, THREADS>>>(src, dst, eat, u, batch,
                                      W1, b1, W2, b2, (float*)d_out, E, B);
}